// round 10
// baseline (speedup 1.0000x reference)
#include <cuda_runtime.h>
#include <math.h>

#define B_  4
#define S_  1024
#define D_  768
#define H_  384
#define NROW (B_*S_)            // 4096
#define BOND_ 3.8f
#define LR_ 0.01f
#define BETA1_ 0.9f
#define BETA2_ 0.999f
#define ADAM_EPS_ 1e-8f
#define NSTEPS_ 50

typedef unsigned long long ull;

// ---------- packed f32x2 helpers (Blackwell FFMA2 path) ----------
__device__ __forceinline__ ull pk2(float lo, float hi) {
    ull r; asm("mov.b64 %0,{%1,%2};" : "=l"(r) : "f"(lo), "f"(hi)); return r;
}
__device__ __forceinline__ void upk2(ull v, float& lo, float& hi) {
    asm("mov.b64 {%0,%1},%2;" : "=f"(lo), "=f"(hi) : "l"(v));
}
__device__ __forceinline__ ull fma2(ull a, ull b, ull c) {
    ull r; asm("fma.rn.f32x2 %0,%1,%2,%3;" : "=l"(r) : "l"(a), "l"(b), "l"(c)); return r;
}
__device__ __forceinline__ ull add2(ull a, ull b) {
    ull r; asm("add.rn.f32x2 %0,%1,%2;" : "=l"(r) : "l"(a), "l"(b)); return r;
}
__device__ __forceinline__ ull mul2(ull a, ull b) {
    ull r; asm("mul.rn.f32x2 %0,%1,%2;" : "=l"(r) : "l"(a), "l"(b)); return r;
}
__device__ __forceinline__ float rsq(float x) {
    float r; asm("rsqrt.approx.f32 %0,%1;" : "=f"(r) : "f"(x)); return r;
}
__device__ __forceinline__ float sqa(float x) {
    float r; asm("sqrt.approx.f32 %0,%1;" : "=f"(r) : "f"(x)); return r;
}
__device__ __forceinline__ float rcpa(float x) {
    float r; asm("rcp.approx.f32 %0,%1;" : "=f"(r) : "f"(x)); return r;
}

// ----- device scratch (no allocations allowed) -----
__device__ float g_h[NROW * H_];               // hidden after ReLU (6 MB)
__device__ float g_delta[NROW * 3];
__device__ float g_pA[3 * NROW];               // ping-pong positions, SoA planes x|y|z
__device__ float g_pB[3 * NROW];
__device__ float g_cms[(size_t)B_ * S_ * S_];  // symmetrized + prescaled contact map (16 MB)
__device__ unsigned g_cnt[B_];                 // per-batch barrier counters
__device__ unsigned g_ph[B_];                  // per-batch barrier phases (monotonic)

__device__ __forceinline__ unsigned ld_acq(const unsigned* p) {
    unsigned v;
    asm volatile("ld.acquire.gpu.global.u32 %0,[%1];" : "=r"(v) : "l"(p) : "memory");
    return v;
}
__device__ __forceinline__ unsigned atom_rel_add(unsigned* p, unsigned a) {
    unsigned v;
    asm volatile("atom.release.gpu.global.add.u32 %0,[%1],%2;"
                 : "=r"(v) : "l"(p), "r"(a) : "memory");
    return v;
}

// =====================================================================
// K1a: g_h = ReLU(A[4096,768] @ W1[768,384] + b1)
// dup-B version: BM=BN=64, BK=16, 128 threads, 8x4/thread.
// Per k: 4 LDS.128 + 16 FFMA2 (80% fma-issue density, zero packing MOVs).
// =====================================================================
__global__ __launch_bounds__(128) void gemm_relu_kernel(
    const float* __restrict__ A, const float* __restrict__ W1,
    const float* __restrict__ b1)
{
    __shared__ float As[16][64];        // k-major, transposed A tile (4 KB)
    __shared__ float Bsd[16][128];      // duplicated B tile (8 KB)

    const int tid = threadIdx.x;
    const int tx = tid & 15;
    const int ty = tid >> 4;
    const int m0 = blockIdx.y * 64;
    const int n0 = blockIdx.x * 64;

    ull acc[4][4];
#pragma unroll
    for (int p = 0; p < 4; p++)
#pragma unroll
        for (int j = 0; j < 4; j++) acc[p][j] = 0ull;

    for (int k0 = 0; k0 < D_; k0 += 16) {
#pragma unroll
        for (int l = 0; l < 2; l++) {
            int idx = tid + l * 128;
            int row = idx >> 2;
            int c4  = idx & 3;
            float4 a = *(const float4*)(A + (size_t)(m0 + row) * D_ + k0 + c4 * 4);
            As[c4 * 4 + 0][row] = a.x;
            As[c4 * 4 + 1][row] = a.y;
            As[c4 * 4 + 2][row] = a.z;
            As[c4 * 4 + 3][row] = a.w;
        }
        {
            int r = tid >> 3;                // 0..15
            int c = (tid & 7) * 8;           // 0..56
            float4 w0 = *(const float4*)(W1 + (size_t)(k0 + r) * H_ + n0 + c);
            float4 w1 = *(const float4*)(W1 + (size_t)(k0 + r) * H_ + n0 + c + 4);
            float* dst = &Bsd[r][2 * c];
            ((float4*)dst)[0] = make_float4(w0.x, w0.x, w0.y, w0.y);
            ((float4*)dst)[1] = make_float4(w0.z, w0.z, w0.w, w0.w);
            ((float4*)dst)[2] = make_float4(w1.x, w1.x, w1.y, w1.y);
            ((float4*)dst)[3] = make_float4(w1.z, w1.z, w1.w, w1.w);
        }
        __syncthreads();

#pragma unroll
        for (int k = 0; k < 16; k++) {
            ulonglong2 a01 = *(const ulonglong2*)&As[k][ty * 8];      // row pairs
            ulonglong2 a23 = *(const ulonglong2*)&As[k][ty * 8 + 4];
            ulonglong2 b01 = *(const ulonglong2*)&Bsd[k][tx * 8];     // dup col pairs
            ulonglong2 b23 = *(const ulonglong2*)&Bsd[k][tx * 8 + 4];
            ull aP[4] = {a01.x, a01.y, a23.x, a23.y};
            ull bD[4] = {b01.x, b01.y, b23.x, b23.y};
#pragma unroll
            for (int p = 0; p < 4; p++)
#pragma unroll
                for (int j = 0; j < 4; j++)
                    acc[p][j] = fma2(aP[p], bD[j], acc[p][j]);
        }
        __syncthreads();
    }

    float4 bias = *(const float4*)(b1 + n0 + tx * 4);
    float bv[4] = {bias.x, bias.y, bias.z, bias.w};
#pragma unroll
    for (int p = 0; p < 4; p++) {
        float lo[4], hi[4];
#pragma unroll
        for (int j = 0; j < 4; j++) upk2(acc[p][j], lo[j], hi[j]);
        int r0 = m0 + ty * 8 + 2 * p;
        float4 o0, o1;
        o0.x = fmaxf(lo[0] + bv[0], 0.f); o0.y = fmaxf(lo[1] + bv[1], 0.f);
        o0.z = fmaxf(lo[2] + bv[2], 0.f); o0.w = fmaxf(lo[3] + bv[3], 0.f);
        o1.x = fmaxf(hi[0] + bv[0], 0.f); o1.y = fmaxf(hi[1] + bv[1], 0.f);
        o1.z = fmaxf(hi[2] + bv[2], 0.f); o1.w = fmaxf(hi[3] + bv[3], 0.f);
        *(float4*)(g_h + (size_t)r0 * H_ + n0 + tx * 4)       = o0;
        *(float4*)(g_h + (size_t)(r0 + 1) * H_ + n0 + tx * 4) = o1;
    }
}

// =====================================================================
// K1b: per-row phi/psi = h @ W2[:,0:2] + b2, then delta vector
// =====================================================================
__global__ __launch_bounds__(128) void angles_delta_kernel(
    const float* __restrict__ W2, const float* __restrict__ b2)
{
    const int row = blockIdx.x;
    const int tid = threadIdx.x;
    const float* h = g_h + (size_t)row * H_;

    float a0 = 0.f, a1 = 0.f;
#pragma unroll
    for (int j = tid; j < H_; j += 128) {
        float hv = h[j];
        a0 = fmaf(hv, W2[j * 3 + 0], a0);
        a1 = fmaf(hv, W2[j * 3 + 1], a1);
    }
#pragma unroll
    for (int off = 16; off; off >>= 1) {
        a0 += __shfl_down_sync(0xffffffffu, a0, off);
        a1 += __shfl_down_sync(0xffffffffu, a1, off);
    }
    __shared__ float s0[4], s1[4];
    int w = tid >> 5, lane = tid & 31;
    if (lane == 0) { s0[w] = a0; s1[w] = a1; }
    __syncthreads();
    if (tid == 0) {
        float phi = s0[0] + s0[1] + s0[2] + s0[3] + b2[0];
        float psi = s1[0] + s1[1] + s1[2] + s1[3] + b2[1];
        float dx, dy, dz;
        if ((row & (S_ - 1)) == 0) {
            dx = dy = dz = 0.f;
        } else {
            float sp, cp, ss, cs;
            sincosf(phi, &sp, &cp);
            sincosf(psi, &ss, &cs);
            dx = BOND_ * cp * cs;
            dy = BOND_ * sp * cs;
            dz = BOND_ * ss;
        }
        g_delta[row * 3 + 0] = dx;
        g_delta[row * 3 + 1] = dy;
        g_delta[row * 3 + 2] = dz;
    }
}

// =====================================================================
// K2: inclusive cumsum per (batch, dim) -> g_pA SoA planes
// =====================================================================
__global__ __launch_bounds__(1024) void cumsum_kernel()
{
    const int b   = blockIdx.x / 3;
    const int dim = blockIdx.x % 3;
    const int s   = threadIdx.x;

    float v = g_delta[((b * S_) + s) * 3 + dim];
    int lane = s & 31, w = s >> 5;
#pragma unroll
    for (int off = 1; off < 32; off <<= 1) {
        float n = __shfl_up_sync(0xffffffffu, v, off);
        if (lane >= off) v += n;
    }
    __shared__ float wsum[32];
    if (lane == 31) wsum[w] = v;
    __syncthreads();
    if (w == 0) {
        float t = wsum[lane];
#pragma unroll
        for (int off = 1; off < 32; off <<= 1) {
            float n = __shfl_up_sync(0xffffffffu, t, off);
            if (lane >= off) t += n;
        }
        wsum[lane] = t;
    }
    __syncthreads();
    float excl = (w == 0) ? 0.f : wsum[w - 1];
    g_pA[dim * NROW + b * S_ + s] = v + excl;
}

// =====================================================================
// K0: cm_sym[b,i,j] = (cm[b,i,j] + cm[b,j,i]) / (B*S*S)
// =====================================================================
__global__ void cmsym_kernel(const float* __restrict__ cm)
{
    __shared__ float ts[32][33];
    const int b  = blockIdx.z;
    const int i0 = blockIdx.y * 32;
    const int j0 = blockIdx.x * 32;
    const float* cb = cm + (size_t)b * S_ * S_;
    float* ob = g_cms + (size_t)b * S_ * S_;
    const int tx = threadIdx.x, ty = threadIdx.y;
    const float invN = 1.0f / (float)((size_t)B_ * S_ * S_);

#pragma unroll
    for (int r = ty; r < 32; r += 8)
        ts[r][tx] = cb[(size_t)(j0 + r) * S_ + i0 + tx];
    __syncthreads();
#pragma unroll
    for (int r = ty; r < 32; r += 8)
        ob[(size_t)(i0 + r) * S_ + j0 + tx] =
            (cb[(size_t)(i0 + r) * S_ + j0 + tx] + ts[tx][r]) * invN;
}

// =====================================================================
// one (row, packed-j-pair) gradient step — f32x2
// =====================================================================
struct PK {
    ull M1, EPS2, N64, SGNM;
};

__device__ __forceinline__ void pair_step(
    ull xj, ull yj, ull zj, ull cj,
    ull xi, ull yi, ull zi,
    ull& g0, ull& g1, ull& g2, const PK& K)
{
    ull dx = fma2(K.M1, xj, xi);
    ull dy = fma2(K.M1, yj, yi);
    ull dz = fma2(K.M1, zj, zi);
    ull d2 = fma2(dx, dx, K.EPS2);
    d2 = fma2(dy, dy, d2);
    d2 = fma2(dz, dz, d2);
    ull sg = add2(d2, K.N64);
    ull cs = cj ^ (sg & K.SGNM);
    float dl, dh; upk2(d2, dl, dh);
    ull inv = pk2(rsq(dl), rsq(dh));
    ull wg = mul2(cs, inv);
    g0 = fma2(wg, dx, g0);
    g1 = fma2(wg, dy, g1);
    g2 = fma2(wg, dz, g2);
}

// =====================================================================
// K3: persistent refine — unchanged from R9 (358 us config):
// 128 blocks x 512 thr, 2 rows/warp, cm rows in smem, LDS.128 inner loop.
// =====================================================================
#define RTH 512
#define BPB 32      // blocks per batch
#define SMEM_REFINE ((3 * S_ + 32 * S_) * (int)sizeof(float))

extern __shared__ float smref[];

__global__ __launch_bounds__(RTH, 1) void refine_kernel(float* __restrict__ out)
{
    float* xs  = smref;
    float* ys  = xs + S_;
    float* zs  = ys + S_;
    float* cmr = zs + S_;     // [32][1024]

    const int tid  = threadIdx.x;
    const int w    = tid >> 5;
    const int lane = tid & 31;
    const int b    = blockIdx.x >> 5;          // /BPB
    const int rbse = (blockIdx.x & 31) * 32;   // row base within batch
    const int rA   = rbse + w * 2;             // warp's rows: rA, rA+1

    // cache this warp's 2 contact-map rows (once; reused 50 steps)
    {
        const float4* sA = (const float4*)(g_cms + ((size_t)b * S_ + rA) * S_);
        const float4* sB = (const float4*)(g_cms + ((size_t)b * S_ + rA + 1) * S_);
        float4* dA = (float4*)(cmr + (size_t)(w * 2) * S_);
        float4* dB = (float4*)(cmr + (size_t)(w * 2 + 1) * S_);
        for (int k = lane; k < S_ / 4; k += 32) { dA[k] = sA[k]; dB[k] = sB[k]; }
    }

    unsigned ph0 = 0;
    if (tid == 0) ph0 = ld_acq(&g_ph[b]);

    float m[2][3] = {{0,0,0},{0,0,0}};
    float v[2][3] = {{0,0,0},{0,0,0}};
    float b1t = 1.f, b2t = 1.f;

    PK K;
    K.M1   = pk2(-1.f, -1.f);
    K.EPS2 = pk2(1e-12f, 1e-12f);
    K.N64  = pk2(-64.f, -64.f);
    K.SGNM = 0x8000000080000000ull;

    const float* cApt = cmr + (size_t)(w * 2) * S_;
    const float* cBpt = cApt + S_;

    for (int t = 1; t <= NSTEPS_; t++) {
        const float* xin = (t & 1) ? g_pA : g_pB;
        float* xout      = (t & 1) ? g_pB : g_pA;

        // reload positions (L2-coherent)
        {
            const float4* px = (const float4*)(xin + 0 * NROW + b * S_);
            const float4* py = (const float4*)(xin + 1 * NROW + b * S_);
            const float4* pz = (const float4*)(xin + 2 * NROW + b * S_);
            for (int i = tid; i < S_ / 4; i += RTH) {
                ((float4*)xs)[i] = __ldcg(px + i);
                ((float4*)ys)[i] = __ldcg(py + i);
                ((float4*)zs)[i] = __ldcg(pz + i);
            }
        }
        __syncthreads();

        const float axA = xs[rA],     ayA = ys[rA],     azA = zs[rA];
        const float axB = xs[rA + 1], ayB = ys[rA + 1], azB = zs[rA + 1];
        const ull xiA = pk2(axA, axA), yiA = pk2(ayA, ayA), ziA = pk2(azA, azA);
        const ull xiB = pk2(axB, axB), yiB = pk2(ayB, ayB), ziB = pk2(azB, azB);

        ull gA0 = 0, gA1 = 0, gA2 = 0;
        ull gB0 = 0, gB1 = 0, gB2 = 0;

        // 8 iterations x 4 j per lane; all tile loads are LDS.128
#pragma unroll
        for (int it = 0; it < 8; it++) {
            const int j = it * 128 + lane * 4;
            const ulonglong2 xj  = *(const ulonglong2*)(xs + j);
            const ulonglong2 yj  = *(const ulonglong2*)(ys + j);
            const ulonglong2 zj  = *(const ulonglong2*)(zs + j);
            const ulonglong2 cjA = *(const ulonglong2*)(cApt + j);
            const ulonglong2 cjB = *(const ulonglong2*)(cBpt + j);

            pair_step(xj.x, yj.x, zj.x, cjA.x, xiA, yiA, ziA, gA0, gA1, gA2, K);
            pair_step(xj.x, yj.x, zj.x, cjB.x, xiB, yiB, ziB, gB0, gB1, gB2, K);
            pair_step(xj.y, yj.y, zj.y, cjA.y, xiA, yiA, ziA, gA0, gA1, gA2, K);
            pair_step(xj.y, yj.y, zj.y, cjB.y, xiB, yiB, ziB, gB0, gB1, gB2, K);
        }

        float gr[2][3];
        {
            float lo, hi;
            upk2(gA0, lo, hi); gr[0][0] = lo + hi;
            upk2(gA1, lo, hi); gr[0][1] = lo + hi;
            upk2(gA2, lo, hi); gr[0][2] = lo + hi;
            upk2(gB0, lo, hi); gr[1][0] = lo + hi;
            upk2(gB1, lo, hi); gr[1][1] = lo + hi;
            upk2(gB2, lo, hi); gr[1][2] = lo + hi;
        }
#pragma unroll
        for (int off = 16; off; off >>= 1) {
            gr[0][0] += __shfl_down_sync(0xffffffffu, gr[0][0], off);
            gr[0][1] += __shfl_down_sync(0xffffffffu, gr[0][1], off);
            gr[0][2] += __shfl_down_sync(0xffffffffu, gr[0][2], off);
            gr[1][0] += __shfl_down_sync(0xffffffffu, gr[1][0], off);
            gr[1][1] += __shfl_down_sync(0xffffffffu, gr[1][1], off);
            gr[1][2] += __shfl_down_sync(0xffffffffu, gr[1][2], off);
        }

        b1t *= BETA1_;
        b2t *= BETA2_;

        if (lane == 0) {
            const float c1f = 1.f / (1.f - b1t);
            const float c2f = 1.f / (1.f - b2t);
            float px[2][3] = {{axA, ayA, azA}, {axB, ayB, azB}};
#pragma unroll
            for (int r = 0; r < 2; r++) {
                float nv[3];
#pragma unroll
                for (int d = 0; d < 3; d++) {
                    m[r][d] = BETA1_ * m[r][d] + (1.f - BETA1_) * gr[r][d];
                    v[r][d] = BETA2_ * v[r][d] + (1.f - BETA2_) * gr[r][d] * gr[r][d];
                    float den = sqa(v[r][d] * c2f) + ADAM_EPS_;
                    nv[d] = px[r][d] - LR_ * (m[r][d] * c1f) * rcpa(den);
                }
                const int row = rA + r;
                if (t == NSTEPS_) {
                    size_t o = ((size_t)b * S_ + row) * 3;
                    out[o + 0] = nv[0];
                    out[o + 1] = nv[1];
                    out[o + 2] = nv[2];
                } else {
                    xout[0 * NROW + b * S_ + row] = nv[0];
                    xout[1 * NROW + b * S_ + row] = nv[1];
                    xout[2 * NROW + b * S_ + row] = nv[2];
                }
            }
        }

        if (t < NSTEPS_) {
            // bar.sync orders all warps' STGs before tid0's release-atomic
            __syncthreads();
            if (tid == 0) {
                unsigned a = atom_rel_add(&g_cnt[b], 1u);
                if (a == (unsigned)(BPB - 1)) {
                    asm volatile("st.relaxed.gpu.global.u32 [%0],%1;"
                                 :: "l"(&g_cnt[b]), "r"(0u) : "memory");
                    (void)atom_rel_add(&g_ph[b], 1u);
                } else {
                    const unsigned target = ph0 + (unsigned)t;
                    while (ld_acq(&g_ph[b]) < target) { }
                }
            }
            __syncthreads();
        }
    }
}

// =====================================================================
// host launcher (graph-capturable: kernel launches only)
// =====================================================================
extern "C" void kernel_launch(void* const* d_in, const int* in_sizes, int n_in,
                              void* d_out, int out_size)
{
    const float* bf  = (const float*)d_in[0];
    const float* cm  = (const float*)d_in[2];
    const float* Wb1 = (const float*)d_in[3];
    const float* bb1 = (const float*)d_in[4];
    const float* Wb2 = (const float*)d_in[5];
    const float* bb2 = (const float*)d_in[6];
    float* out = (float*)d_out;

    static int smem_set = 0;
    if (!smem_set) {
        cudaFuncSetAttribute(refine_kernel,
                             cudaFuncAttributeMaxDynamicSharedMemorySize, SMEM_REFINE);
        smem_set = 1;
    }

    gemm_relu_kernel<<<dim3(H_ / 64, NROW / 64), 128>>>(bf, Wb1, bb1);
    angles_delta_kernel<<<NROW, 128>>>(Wb2, bb2);
    cmsym_kernel<<<dim3(S_ / 32, S_ / 32, B_), dim3(32, 8)>>>(cm);
    cumsum_kernel<<<B_ * 3, S_>>>();
    refine_kernel<<<128, RTH, SMEM_REFINE>>>(out);
}

// round 11
// speedup vs baseline: 1.2059x; 1.2059x over previous
#include <cuda_runtime.h>
#include <math.h>

#define B_  4
#define S_  1024
#define D_  768
#define H_  384
#define NROW (B_*S_)            // 4096
#define BOND_ 3.8f
#define LR_ 0.01f
#define BETA1_ 0.9f
#define BETA2_ 0.999f
#define ADAM_EPS_ 1e-8f
#define NSTEPS_ 50

typedef unsigned long long ull;

// ---------- packed f32x2 helpers (Blackwell FFMA2 path) ----------
__device__ __forceinline__ ull pk2(float lo, float hi) {
    ull r; asm("mov.b64 %0,{%1,%2};" : "=l"(r) : "f"(lo), "f"(hi)); return r;
}
__device__ __forceinline__ void upk2(ull v, float& lo, float& hi) {
    asm("mov.b64 {%0,%1},%2;" : "=f"(lo), "=f"(hi) : "l"(v));
}
__device__ __forceinline__ ull fma2(ull a, ull b, ull c) {
    ull r; asm("fma.rn.f32x2 %0,%1,%2,%3;" : "=l"(r) : "l"(a), "l"(b), "l"(c)); return r;
}
__device__ __forceinline__ ull add2(ull a, ull b) {
    ull r; asm("add.rn.f32x2 %0,%1,%2;" : "=l"(r) : "l"(a), "l"(b)); return r;
}
__device__ __forceinline__ ull mul2(ull a, ull b) {
    ull r; asm("mul.rn.f32x2 %0,%1,%2;" : "=l"(r) : "l"(a), "l"(b)); return r;
}
__device__ __forceinline__ float rsq(float x) {
    float r; asm("rsqrt.approx.f32 %0,%1;" : "=f"(r) : "f"(x)); return r;
}
__device__ __forceinline__ float sqa(float x) {
    float r; asm("sqrt.approx.f32 %0,%1;" : "=f"(r) : "f"(x)); return r;
}
__device__ __forceinline__ float rcpa(float x) {
    float r; asm("rcp.approx.f32 %0,%1;" : "=f"(r) : "f"(x)); return r;
}

// ----- device scratch (no allocations allowed) -----
__device__ float g_h[NROW * H_];               // hidden after ReLU (6 MB)
__device__ float g_delta[NROW * 3];
__device__ float g_pA[3 * NROW];               // ping-pong positions, SoA planes x|y|z
__device__ float g_pB[3 * NROW];
__device__ float g_cms[(size_t)B_ * S_ * S_];  // symmetrized + prescaled contact map (16 MB)
__device__ unsigned g_flag[128 * 32];          // per-block step flags, 128B-strided slots

__device__ __forceinline__ unsigned ld_acq(const unsigned* p) {
    unsigned v;
    asm volatile("ld.acquire.gpu.global.u32 %0,[%1];" : "=r"(v) : "l"(p) : "memory");
    return v;
}
__device__ __forceinline__ void st_rel(unsigned* p, unsigned v) {
    asm volatile("st.release.gpu.global.u32 [%0],%1;" :: "l"(p), "r"(v) : "memory");
}

// =====================================================================
// K1a: g_h = ReLU(A[4096,768] @ W1[768,384] + b1)   (R9 version — proven)
// =====================================================================
__global__ __launch_bounds__(256) void gemm_relu_kernel(
    const float* __restrict__ A, const float* __restrict__ W1,
    const float* __restrict__ b1)
{
    __shared__ float As[16][64];
    __shared__ float Bs[16][64];

    const int tid = threadIdx.x;
    const int tx = tid & 15;
    const int ty = tid >> 4;
    const int m0 = blockIdx.y * 64;
    const int n0 = blockIdx.x * 64;

    ull acc[4][2];
#pragma unroll
    for (int i = 0; i < 4; i++) { acc[i][0] = 0ull; acc[i][1] = 0ull; }

    for (int k0 = 0; k0 < D_; k0 += 16) {
        {
            int row = tid >> 2;
            int c4  = tid & 3;
            float4 a = *(const float4*)(A + (size_t)(m0 + row) * D_ + k0 + c4 * 4);
            As[c4 * 4 + 0][row] = a.x;
            As[c4 * 4 + 1][row] = a.y;
            As[c4 * 4 + 2][row] = a.z;
            As[c4 * 4 + 3][row] = a.w;
        }
        {
            int row = tid >> 4;
            int c4  = tid & 15;
            *(float4*)&Bs[row][c4 * 4] =
                *(const float4*)(W1 + (size_t)(k0 + row) * H_ + n0 + c4 * 4);
        }
        __syncthreads();

#pragma unroll
        for (int k = 0; k < 16; k++) {
            float a[4], bb[4];
            *(float4*)a  = *(const float4*)&As[k][ty * 4];
            *(float4*)bb = *(const float4*)&Bs[k][tx * 4];
            ull b01 = pk2(bb[0], bb[1]);
            ull b23 = pk2(bb[2], bb[3]);
#pragma unroll
            for (int i = 0; i < 4; i++) {
                ull ai = pk2(a[i], a[i]);
                acc[i][0] = fma2(ai, b01, acc[i][0]);
                acc[i][1] = fma2(ai, b23, acc[i][1]);
            }
        }
        __syncthreads();
    }

    float4 bias = *(const float4*)(b1 + n0 + tx * 4);
#pragma unroll
    for (int i = 0; i < 4; i++) {
        float v0, v1, v2, v3;
        upk2(acc[i][0], v0, v1);
        upk2(acc[i][1], v2, v3);
        float4 o;
        o.x = fmaxf(v0 + bias.x, 0.f);
        o.y = fmaxf(v1 + bias.y, 0.f);
        o.z = fmaxf(v2 + bias.z, 0.f);
        o.w = fmaxf(v3 + bias.w, 0.f);
        *(float4*)(g_h + (size_t)(m0 + ty * 4 + i) * H_ + n0 + tx * 4) = o;
    }
}

// =====================================================================
// K1b: per-row phi/psi = h @ W2[:,0:2] + b2, then delta vector
// =====================================================================
__global__ __launch_bounds__(128) void angles_delta_kernel(
    const float* __restrict__ W2, const float* __restrict__ b2)
{
    const int row = blockIdx.x;
    const int tid = threadIdx.x;
    const float* h = g_h + (size_t)row * H_;

    float a0 = 0.f, a1 = 0.f;
#pragma unroll
    for (int j = tid; j < H_; j += 128) {
        float hv = h[j];
        a0 = fmaf(hv, W2[j * 3 + 0], a0);
        a1 = fmaf(hv, W2[j * 3 + 1], a1);
    }
#pragma unroll
    for (int off = 16; off; off >>= 1) {
        a0 += __shfl_down_sync(0xffffffffu, a0, off);
        a1 += __shfl_down_sync(0xffffffffu, a1, off);
    }
    __shared__ float s0[4], s1[4];
    int w = tid >> 5, lane = tid & 31;
    if (lane == 0) { s0[w] = a0; s1[w] = a1; }
    __syncthreads();
    if (tid == 0) {
        float phi = s0[0] + s0[1] + s0[2] + s0[3] + b2[0];
        float psi = s1[0] + s1[1] + s1[2] + s1[3] + b2[1];
        float dx, dy, dz;
        if ((row & (S_ - 1)) == 0) {
            dx = dy = dz = 0.f;
        } else {
            float sp, cp, ss, cs;
            sincosf(phi, &sp, &cp);
            sincosf(psi, &ss, &cs);
            dx = BOND_ * cp * cs;
            dy = BOND_ * sp * cs;
            dz = BOND_ * ss;
        }
        g_delta[row * 3 + 0] = dx;
        g_delta[row * 3 + 1] = dy;
        g_delta[row * 3 + 2] = dz;
    }
}

// =====================================================================
// K2: inclusive cumsum per (batch, dim) -> g_pA SoA planes
// =====================================================================
__global__ __launch_bounds__(1024) void cumsum_kernel()
{
    const int b   = blockIdx.x / 3;
    const int dim = blockIdx.x % 3;
    const int s   = threadIdx.x;

    float v = g_delta[((b * S_) + s) * 3 + dim];
    int lane = s & 31, w = s >> 5;
#pragma unroll
    for (int off = 1; off < 32; off <<= 1) {
        float n = __shfl_up_sync(0xffffffffu, v, off);
        if (lane >= off) v += n;
    }
    __shared__ float wsum[32];
    if (lane == 31) wsum[w] = v;
    __syncthreads();
    if (w == 0) {
        float t = wsum[lane];
#pragma unroll
        for (int off = 1; off < 32; off <<= 1) {
            float n = __shfl_up_sync(0xffffffffu, t, off);
            if (lane >= off) t += n;
        }
        wsum[lane] = t;
    }
    __syncthreads();
    float excl = (w == 0) ? 0.f : wsum[w - 1];
    g_pA[dim * NROW + b * S_ + s] = v + excl;
}

// =====================================================================
// K0: cm_sym[b,i,j] = (cm[b,i,j] + cm[b,j,i]) / (B*S*S)
// =====================================================================
__global__ void cmsym_kernel(const float* __restrict__ cm)
{
    __shared__ float ts[32][33];
    const int b  = blockIdx.z;
    const int i0 = blockIdx.y * 32;
    const int j0 = blockIdx.x * 32;
    const float* cb = cm + (size_t)b * S_ * S_;
    float* ob = g_cms + (size_t)b * S_ * S_;
    const int tx = threadIdx.x, ty = threadIdx.y;
    const float invN = 1.0f / (float)((size_t)B_ * S_ * S_);

#pragma unroll
    for (int r = ty; r < 32; r += 8)
        ts[r][tx] = cb[(size_t)(j0 + r) * S_ + i0 + tx];
    __syncthreads();
#pragma unroll
    for (int r = ty; r < 32; r += 8)
        ob[(size_t)(i0 + r) * S_ + j0 + tx] =
            (cb[(size_t)(i0 + r) * S_ + j0 + tx] + ts[tx][r]) * invN;
}

// =====================================================================
// one (row, packed-j-pair) gradient step — f32x2.
// sign(d2-64) via integer compare (positive floats: IEEE order == int
// order), moving the subtract off the saturated FMA pipe onto ALU.
// Bit-identical to the float-subtract version.
// =====================================================================
struct PK {
    ull M1, EPS2;
};

__device__ __forceinline__ void pair_step(
    ull xj, ull yj, ull zj, ull cj,
    ull xi, ull yi, ull zi,
    ull& g0, ull& g1, ull& g2, const PK& K)
{
    ull dx = fma2(K.M1, xj, xi);
    ull dy = fma2(K.M1, yj, yi);
    ull dz = fma2(K.M1, zj, zi);
    ull d2 = fma2(dx, dx, K.EPS2);
    d2 = fma2(dy, dy, d2);
    d2 = fma2(dz, dz, d2);
    float dl, dh; upk2(d2, dl, dh);
    // flip-mask = sign of (bits(d2) - bits(64.0f)); ALU-pipe IADD+LOP3
    unsigned il = __float_as_uint(dl), ih = __float_as_uint(dh);
    unsigned csl = ((il - 0x42800000u) & 0x80000000u) ^ (unsigned)cj;
    unsigned csh = ((ih - 0x42800000u) & 0x80000000u) ^ (unsigned)(cj >> 32);
    ull cs = ((ull)csh << 32) | (ull)csl;
    ull inv = pk2(rsq(dl), rsq(dh));
    ull wg = mul2(cs, inv);
    g0 = fma2(wg, dx, g0);
    g1 = fma2(wg, dy, g1);
    g2 = fma2(wg, dz, g2);
}

// =====================================================================
// K3: persistent refine — R9 shape (128 blocks x 512 thr, 2 rows/warp,
// cm rows in smem, LDS.128 inner loop). Barrier = per-block release
// flags in distinct 128B lines; warp 0 lanes spin on peer flags
// (no contended atomics, monotonic counters -> replay-safe).
// =====================================================================
#define RTH 512
#define BPB 32      // blocks per batch
#define SMEM_REFINE ((3 * S_ + 32 * S_) * (int)sizeof(float))

extern __shared__ float smref[];

__global__ __launch_bounds__(RTH, 1) void refine_kernel(float* __restrict__ out)
{
    float* xs  = smref;
    float* ys  = xs + S_;
    float* zs  = ys + S_;
    float* cmr = zs + S_;     // [32][1024]

    const int tid  = threadIdx.x;
    const int w    = tid >> 5;
    const int lane = tid & 31;
    const int b    = blockIdx.x >> 5;          // /BPB
    const int rbse = (blockIdx.x & 31) * 32;   // row base within batch
    const int rA   = rbse + w * 2;             // warp's rows: rA, rA+1

    // cache this warp's 2 contact-map rows (once; reused 50 steps)
    {
        const float4* sA = (const float4*)(g_cms + ((size_t)b * S_ + rA) * S_);
        const float4* sB = (const float4*)(g_cms + ((size_t)b * S_ + rA + 1) * S_);
        float4* dA = (float4*)(cmr + (size_t)(w * 2) * S_);
        float4* dB = (float4*)(cmr + (size_t)(w * 2 + 1) * S_);
        for (int k = lane; k < S_ / 4; k += 32) { dA[k] = sA[k]; dB[k] = sB[k]; }
    }

    // barrier state: my slot + per-lane peer slot (warp 0 only does waits)
    unsigned* myflag = &g_flag[(unsigned)blockIdx.x * 32u];
    unsigned* peerflag = &g_flag[(unsigned)(b * BPB + lane) * 32u];
    unsigned mybase = 0, peerbase = 0;
    if (tid == 0) mybase = ld_acq(myflag);
    if (w == 0) peerbase = ld_acq(peerflag);

    float m[2][3] = {{0,0,0},{0,0,0}};
    float v[2][3] = {{0,0,0},{0,0,0}};
    float b1t = 1.f, b2t = 1.f;

    PK K;
    K.M1   = pk2(-1.f, -1.f);
    K.EPS2 = pk2(1e-12f, 1e-12f);

    const float* cApt = cmr + (size_t)(w * 2) * S_;
    const float* cBpt = cApt + S_;

    for (int t = 1; t <= NSTEPS_; t++) {
        const float* xin = (t & 1) ? g_pA : g_pB;
        float* xout      = (t & 1) ? g_pB : g_pA;

        // reload positions (L2-coherent)
        {
            const float4* px = (const float4*)(xin + 0 * NROW + b * S_);
            const float4* py = (const float4*)(xin + 1 * NROW + b * S_);
            const float4* pz = (const float4*)(xin + 2 * NROW + b * S_);
            for (int i = tid; i < S_ / 4; i += RTH) {
                ((float4*)xs)[i] = __ldcg(px + i);
                ((float4*)ys)[i] = __ldcg(py + i);
                ((float4*)zs)[i] = __ldcg(pz + i);
            }
        }
        __syncthreads();

        const float axA = xs[rA],     ayA = ys[rA],     azA = zs[rA];
        const float axB = xs[rA + 1], ayB = ys[rA + 1], azB = zs[rA + 1];
        const ull xiA = pk2(axA, axA), yiA = pk2(ayA, ayA), ziA = pk2(azA, azA);
        const ull xiB = pk2(axB, axB), yiB = pk2(ayB, ayB), ziB = pk2(azB, azB);

        ull gA0 = 0, gA1 = 0, gA2 = 0;
        ull gB0 = 0, gB1 = 0, gB2 = 0;

        // 8 iterations x 4 j per lane; all tile loads are LDS.128
#pragma unroll
        for (int it = 0; it < 8; it++) {
            const int j = it * 128 + lane * 4;
            const ulonglong2 xj  = *(const ulonglong2*)(xs + j);
            const ulonglong2 yj  = *(const ulonglong2*)(ys + j);
            const ulonglong2 zj  = *(const ulonglong2*)(zs + j);
            const ulonglong2 cjA = *(const ulonglong2*)(cApt + j);
            const ulonglong2 cjB = *(const ulonglong2*)(cBpt + j);

            pair_step(xj.x, yj.x, zj.x, cjA.x, xiA, yiA, ziA, gA0, gA1, gA2, K);
            pair_step(xj.x, yj.x, zj.x, cjB.x, xiB, yiB, ziB, gB0, gB1, gB2, K);
            pair_step(xj.y, yj.y, zj.y, cjA.y, xiA, yiA, ziA, gA0, gA1, gA2, K);
            pair_step(xj.y, yj.y, zj.y, cjB.y, xiB, yiB, ziB, gB0, gB1, gB2, K);
        }

        float gr[2][3];
        {
            float lo, hi;
            upk2(gA0, lo, hi); gr[0][0] = lo + hi;
            upk2(gA1, lo, hi); gr[0][1] = lo + hi;
            upk2(gA2, lo, hi); gr[0][2] = lo + hi;
            upk2(gB0, lo, hi); gr[1][0] = lo + hi;
            upk2(gB1, lo, hi); gr[1][1] = lo + hi;
            upk2(gB2, lo, hi); gr[1][2] = lo + hi;
        }
#pragma unroll
        for (int off = 16; off; off >>= 1) {
            gr[0][0] += __shfl_down_sync(0xffffffffu, gr[0][0], off);
            gr[0][1] += __shfl_down_sync(0xffffffffu, gr[0][1], off);
            gr[0][2] += __shfl_down_sync(0xffffffffu, gr[0][2], off);
            gr[1][0] += __shfl_down_sync(0xffffffffu, gr[1][0], off);
            gr[1][1] += __shfl_down_sync(0xffffffffu, gr[1][1], off);
            gr[1][2] += __shfl_down_sync(0xffffffffu, gr[1][2], off);
        }

        b1t *= BETA1_;
        b2t *= BETA2_;

        if (lane == 0) {
            const float c1f = 1.f / (1.f - b1t);
            const float c2f = 1.f / (1.f - b2t);
            float px[2][3] = {{axA, ayA, azA}, {axB, ayB, azB}};
#pragma unroll
            for (int r = 0; r < 2; r++) {
                float nv[3];
#pragma unroll
                for (int d = 0; d < 3; d++) {
                    m[r][d] = BETA1_ * m[r][d] + (1.f - BETA1_) * gr[r][d];
                    v[r][d] = BETA2_ * v[r][d] + (1.f - BETA2_) * gr[r][d] * gr[r][d];
                    float den = sqa(v[r][d] * c2f) + ADAM_EPS_;
                    nv[d] = px[r][d] - LR_ * (m[r][d] * c1f) * rcpa(den);
                }
                const int row = rA + r;
                if (t == NSTEPS_) {
                    size_t o = ((size_t)b * S_ + row) * 3;
                    out[o + 0] = nv[0];
                    out[o + 1] = nv[1];
                    out[o + 2] = nv[2];
                } else {
                    xout[0 * NROW + b * S_ + row] = nv[0];
                    xout[1 * NROW + b * S_ + row] = nv[1];
                    xout[2 * NROW + b * S_ + row] = nv[2];
                }
            }
        }

        if (t < NSTEPS_) {
            // bar.sync orders all warps' STGs before tid0's release-store
            __syncthreads();
            if (tid == 0) st_rel(myflag, mybase + (unsigned)t);
            if (w == 0) {
                const unsigned tgt = peerbase + (unsigned)t;
                while (ld_acq(peerflag) < tgt) { }
            }
            __syncthreads();
        }
    }
}

// =====================================================================
// host launcher (graph-capturable: kernel launches only)
// =====================================================================
extern "C" void kernel_launch(void* const* d_in, const int* in_sizes, int n_in,
                              void* d_out, int out_size)
{
    const float* bf  = (const float*)d_in[0];
    const float* cm  = (const float*)d_in[2];
    const float* Wb1 = (const float*)d_in[3];
    const float* bb1 = (const float*)d_in[4];
    const float* Wb2 = (const float*)d_in[5];
    const float* bb2 = (const float*)d_in[6];
    float* out = (float*)d_out;

    static int smem_set = 0;
    if (!smem_set) {
        cudaFuncSetAttribute(refine_kernel,
                             cudaFuncAttributeMaxDynamicSharedMemorySize, SMEM_REFINE);
        smem_set = 1;
    }

    gemm_relu_kernel<<<dim3(H_ / 64, NROW / 64), 256>>>(bf, Wb1, bb1);
    angles_delta_kernel<<<NROW, 128>>>(Wb2, bb2);
    cmsym_kernel<<<dim3(S_ / 32, S_ / 32, B_), dim3(32, 8)>>>(cm);
    cumsum_kernel<<<B_ * 3, S_>>>();
    refine_kernel<<<128, RTH, SMEM_REFINE>>>(out);
}